// round 9
// baseline (speedup 1.0000x reference)
#include <cuda_runtime.h>
#include <cstdint>
#include <cstddef>

#define MAXN      262144
#define HBITS     19
#define HSIZE     (1u<<HBITS)
#define HMASK     (HSIZE-1u)
#define HIST_SIZE 262144
#define CAND_CAP  4096
#define LF        96
#define DF        32
#define TOPK      128
#define BPTS      256
#define FLIP_MASK 0x0u   // verified: low-index-first tie order

__device__ unsigned long long g_h2_keys[HSIZE];
__device__ int                g_h2_min[HSIZE];
__device__ unsigned long long g_comp[MAXN];
__device__ int                g_hist[HIST_SIZE];
__device__ unsigned long long g_cand[CAND_CAP];
__device__ int                g_cnt3[4];
__device__ int                g_widx[TOPK];
__device__ float              g_wconf[TOPK];
__device__ int                g_wc4[TOPK*4];
__device__ float              g_pool[(size_t)TOPK*27*LF];
__device__ int                g_cellpts[TOPK*27];
__device__ float              g_cdesc[129*DF];

// Reference _encode overflows int32 (jax x64 disabled): b*2048^3 mod 2^32 == 0,
// so keys are batch-BLIND; (x,y,z) stays injective. Mirror that: encode xyz only.
__device__ __forceinline__ unsigned long long enc3(int x, int y, int z) {
    return ((unsigned long long)(unsigned)(x + 512) << 22)
         | ((unsigned long long)(unsigned)(y + 512) << 11)
         |  (unsigned long long)(unsigned)(z + 512);
}
__device__ __forceinline__ unsigned int hashk(unsigned long long k) {
    k *= 0x9E3779B97F4A7C15ull;
    return (unsigned int)(k >> (64 - HBITS));
}
__device__ __forceinline__ int h_lookup(const unsigned long long* tab, unsigned long long key) {
    unsigned int s = hashk(key);
    for (;;) {
        unsigned long long k = tab[s];
        if (k == key) return (int)s;
        if (k == ~0ull) return -1;
        s = (s + 1) & HMASK;
    }
}

__global__ void k_h2_insert(const int* __restrict__ coords, const float* __restrict__ scores, int N) {
    int i = blockIdx.x * blockDim.x + threadIdx.x;
    if (i >= N) return;
    if (!(scores[i] > 0.1f)) return;
    unsigned long long key = enc3(coords[4*i+1], coords[4*i+2], coords[4*i+3]);
    unsigned int s = hashk(key);
    for (;;) {
        unsigned long long prev = atomicCAS(&g_h2_keys[s], ~0ull, key);
        if (prev == ~0ull || prev == key) {
            atomicMin(&g_h2_min[s], i);
            return;
        }
        s = (s + 1) & HMASK;
    }
}

__global__ void k_peaks(const int* __restrict__ coords, const float* __restrict__ scores, int N) {
    int i = blockIdx.x * blockDim.x + threadIdx.x;
    if (i >= N) return;
    float sc = scores[i];
    if (!(sc > 0.1f)) { g_comp[i] = 0ull; return; }
    int x = coords[4*i+1], y = coords[4*i+2], z = coords[4*i+3];
    float hmax = -1.0f;
    #pragma unroll
    for (int dx = -1; dx <= 1; dx++)
    #pragma unroll
    for (int dy = -1; dy <= 1; dy++)
    #pragma unroll
    for (int dz = -1; dz <= 1; dz++) {
        int s = h_lookup(g_h2_keys, enc3(x+dx, y+dy, z+dz));
        if (s >= 0) hmax = fmaxf(hmax, scores[g_h2_min[s]]);
    }
    if (hmax == sc) {
        unsigned int sb = __float_as_uint(sc);
        g_comp[i] = ((unsigned long long)sb << 32) | (unsigned long long)(0xFFFFFFFFu - (unsigned int)i);
        atomicAdd(&g_hist[sb >> 12], 1);
    } else {
        g_comp[i] = 0ull;
    }
}

__global__ void k_thresh() {
    __shared__ int ssum[1024];
    __shared__ int cumsh;
    int t = threadIdx.x;
    if (t == 0) cumsh = 0;
    __syncthreads();
    for (int base = HIST_SIZE - 1024; base >= 0; base -= 1024) {
        ssum[t] = g_hist[base + t];
        __syncthreads();
        for (int o = 512; o > 0; o >>= 1) { if (t < o) ssum[t] += ssum[t + o]; __syncthreads(); }
        int chunk = ssum[0];
        int cum0 = cumsh;
        __syncthreads();
        if (cum0 + chunk >= TOPK) {
            if (t == 0) {
                int cum = cum0;
                for (int i2 = 1023; i2 >= 0; i2--) {
                    cum += g_hist[base + i2];
                    if (cum >= TOPK) { g_cnt3[2] = base + i2; break; }
                }
            }
            return;
        }
        if (t == 0) cumsh = cum0 + chunk;
        __syncthreads();
    }
}

__global__ void k_collect(int N) {
    int i = blockIdx.x * blockDim.x + threadIdx.x;
    if (i >= N) return;
    unsigned long long c = g_comp[i];
    if (c == 0ull) return;
    if ((int)(c >> 44) >= g_cnt3[2]) {
        int p = atomicAdd(&g_cnt3[1], 1);
        if (p < CAND_CAP) g_cand[p] = c;
    }
}

__global__ void k_select(float* __restrict__ conf_out) {
    __shared__ unsigned long long s[CAND_CAP];
    int t = threadIdx.x;
    int n = g_cnt3[1]; if (n > CAND_CAP) n = CAND_CAP;
    for (int i = t; i < CAND_CAP; i += 1024) s[i] = (i < n) ? g_cand[i] : 0ull;
    __syncthreads();
    for (int k = 2; k <= CAND_CAP; k <<= 1) {
        for (int j = k >> 1; j > 0; j >>= 1) {
            for (int i = t; i < CAND_CAP; i += 1024) {
                int l = i ^ j;
                if (l > i) {
                    unsigned long long a = s[i], b = s[l];
                    bool up = ((i & k) == 0);
                    if (up ? (a < b) : (a > b)) { s[i] = b; s[l] = a; }
                }
            }
            __syncthreads();
        }
    }
#if FLIP_MASK
    if (t == 0) {
        const int SCAN = 192;
        int gidx = 0, a = 0;
        for (int r = 1; r <= SCAN; r++) {
            bool cont = false;
            if (r < SCAN && s[r] != 0ull)
                cont = ((unsigned)(s[r] >> 32) == (unsigned)(s[a] >> 32));
            if (!cont) {
                int len = r - a;
                if (len >= 2 && a < TOPK) {
                    if ((FLIP_MASK >> gidx) & 1u) {
                        int lo = a, hi = r - 1;
                        while (lo < hi) {
                            unsigned long long tmp = s[lo]; s[lo] = s[hi]; s[hi] = tmp;
                            lo++; hi--;
                        }
                    }
                    gidx++;
                }
                a = r;
            }
        }
    }
    __syncthreads();
#endif
    if (t < TOPK) {
        unsigned long long c = s[t];
        if (c != 0ull) {
            float sc = __uint_as_float((unsigned int)(c >> 32));
            g_wconf[t] = sc;
            g_widx[t]  = (int)(0xFFFFFFFFu - (unsigned int)(c & 0xFFFFFFFFull));
            conf_out[t] = sc;
        } else {
            g_wconf[t] = 0.0f; g_widx[t] = -1; conf_out[t] = 0.0f;
        }
    }
}

__global__ void k_wc(const int* __restrict__ coords, const float* __restrict__ offs) {
    int k = threadIdx.x;
    int idx = g_widx[k];
    int4 w;
    if (idx < 0) {
        w.x = w.y = w.z = w.w = 0x40000000;
    } else {
        w.x = 0; // batch ignored (reference keys are batch-blind)
        w.y = coords[4*idx+1] + (int)offs[3*idx];
        w.z = coords[4*idx+2] + (int)offs[3*idx+1];
        w.w = coords[4*idx+3] + (int)offs[3*idx+2];
    }
    ((int4*)g_wc4)[k] = w;
}

__global__ void k_match(const int* __restrict__ coords, const float* __restrict__ offs,
                        const float* __restrict__ feats, int N) {
    __shared__ int4 swc[TOPK];
    int tid = threadIdx.x;
    if (tid < TOPK) swc[tid] = ((const int4*)g_wc4)[tid];
    __syncthreads();
    int i = blockIdx.x * blockDim.x + tid;
    if (i >= N) return;
    int nx = coords[4*i+1] + (int)offs[3*i];
    int ny = coords[4*i+2] + (int)offs[3*i+1];
    int nz = coords[4*i+3] + (int)offs[3*i+2];
    #pragma unroll 4
    for (int k = 0; k < TOPK; k++) {
        int4 w = swc[k];
        int dx = nx - w.y, dy = ny - w.z, dz = nz - w.w;
        if ((unsigned)(dx+1) <= 2u && (unsigned)(dy+1) <= 2u && (unsigned)(dz+1) <= 2u) {
            int o = (dx+1)*9 + (dy+1)*3 + (dz+1);
            atomicAdd(&g_cellpts[k*27 + o], 1);
            float* dst = &g_pool[((size_t)(k*27 + o))*LF];
            const float* src = feats + (size_t)i*LF;
            for (int l = 0; l < LF; l++) atomicAdd(&dst[l], src[l]);
        }
    }
}

__global__ void k_cdesc(const float* __restrict__ W, const float* __restrict__ bg) {
    int j = blockIdx.x;
    int t = threadIdx.x;
    __shared__ float pool[LF];
    if (j == 0) {
        if (t < DF) g_cdesc[t] = bg[t];
        return;
    }
    int k = j - 1;
    if (g_widx[k] < 0) {
        if (t < DF) g_cdesc[j*DF + t] = 0.0f;
        return;
    }
    float acc = 0.0f;
    int m = 0;
    #pragma unroll
    for (int o = 0; o < 27; o++) {
        int c = g_cellpts[k*27 + o];
        if (c > 0) { acc += g_pool[((size_t)(k*27 + o))*LF + t] / (float)c; m++; }
    }
    pool[t] = acc / (float)m;
    __syncthreads();
    if (t < DF) {
        float sacc = 0.0f;
        #pragma unroll 8
        for (int l = 0; l < LF; l++) sacc += pool[l] * W[l*DF + t];
        g_cdesc[j*DF + t] = fmaxf(sacc, 0.0f) * g_wconf[k];
    }
}

#define SMEM_SW   (LF*DF)
#define SMEM_SC   (129*36)
#define SMEM_SO   (BPTS*33)
#define SMEM_FINAL ((SMEM_SW + SMEM_SC + SMEM_SO) * (int)sizeof(float))

__global__ void k_final(const float* __restrict__ feats, const float* __restrict__ W,
                        float* __restrict__ inst, int N) {
    extern __shared__ float sm[];
    float* sW = sm;
    float* sC = sm + SMEM_SW;
    float* sO = sm + SMEM_SW + SMEM_SC;
    int tid = threadIdx.x;
    for (int i = tid; i < LF*DF; i += BPTS) sW[i] = W[i];
    for (int i = tid; i < 129*36; i += BPTS) {
        int j = i / 36, d = i % 36;
        sC[i] = (d < DF) ? g_cdesc[j*DF + d] : 0.0f;
    }
    __syncthreads();

    int p0 = blockIdx.x * BPTS;
    int i = p0 + tid;
    float h[DF];
    #pragma unroll
    for (int d = 0; d < DF; d++) h[d] = 0.0f;

    if (i < N) {
        const float4* f4 = (const float4*)(feats + (size_t)i * LF);
        #pragma unroll 4
        for (int l4 = 0; l4 < LF/4; l4++) {
            float4 f = f4[l4];
            int l = l4 * 4;
            #pragma unroll
            for (int d4 = 0; d4 < DF/4; d4++) {
                float4 w0 = *(const float4*)&sW[(l+0)*DF + d4*4];
                float4 w1 = *(const float4*)&sW[(l+1)*DF + d4*4];
                float4 w2 = *(const float4*)&sW[(l+2)*DF + d4*4];
                float4 w3 = *(const float4*)&sW[(l+3)*DF + d4*4];
                h[d4*4+0] += f.x*w0.x + f.y*w1.x + f.z*w2.x + f.w*w3.x;
                h[d4*4+1] += f.x*w0.y + f.y*w1.y + f.z*w2.y + f.w*w3.y;
                h[d4*4+2] += f.x*w0.z + f.y*w1.z + f.z*w2.z + f.w*w3.z;
                h[d4*4+3] += f.x*w0.w + f.y*w1.w + f.z*w2.w + f.w*w3.w;
            }
        }
        #pragma unroll
        for (int d = 0; d < DF; d++) h[d] = fmaxf(h[d], 0.0f);
    }

    int np = N - p0; if (np > BPTS) np = BPTS;

    for (int jc = 0; jc < 128; jc += 32) {
        if (i < N) {
            #pragma unroll 4
            for (int jj = 0; jj < 32; jj += 2) {
                int j0 = jc + jj;
                float s0 = 0.0f, s1 = 0.0f;
                #pragma unroll
                for (int d4 = 0; d4 < DF/4; d4++) {
                    float4 c0 = *(const float4*)&sC[j0*36 + d4*4];
                    float4 c1 = *(const float4*)&sC[(j0+1)*36 + d4*4];
                    s0 += h[d4*4+0]*c0.x + h[d4*4+1]*c0.y + h[d4*4+2]*c0.z + h[d4*4+3]*c0.w;
                    s1 += h[d4*4+0]*c1.x + h[d4*4+1]*c1.y + h[d4*4+2]*c1.z + h[d4*4+3]*c1.w;
                }
                sO[tid*33 + jj]     = s0;
                sO[tid*33 + jj + 1] = s1;
            }
        }
        __syncthreads();
        for (int e = tid; e < np*32; e += BPTS) {
            int p = e >> 5, j0 = e & 31;
            inst[(size_t)(p0 + p) * 129 + jc + j0] = sO[p*33 + j0];
        }
        __syncthreads();
    }
    if (i < N) {
        float s = 0.0f;
        #pragma unroll
        for (int d4 = 0; d4 < DF/4; d4++) {
            float4 c = *(const float4*)&sC[128*36 + d4*4];
            s += h[d4*4+0]*c.x + h[d4*4+1]*c.y + h[d4*4+2]*c.z + h[d4*4+3]*c.w;
        }
        inst[(size_t)i*129 + 128] = s;
    }
}

extern "C" void kernel_launch(void* const* d_in, const int* in_sizes, int n_in,
                              void* d_out, int out_size) {
    const int*   coords = (const int*)d_in[0];
    const float* feats  = (const float*)d_in[1];
    const float* scores = (const float*)d_in[2];
    const float* offs   = (const float*)d_in[3];
    const float* W      = (const float*)d_in[4];
    const float* bg     = (const float*)d_in[5];
    int N = in_sizes[0] / 4;
    float* out = (float*)d_out;
    size_t base = (size_t)out_size - (size_t)N * 129;
    float* inst = out + base;

    void *p_h2k, *p_h2m, *p_hist, *p_cnt, *p_pool, *p_cp;
    cudaGetSymbolAddress(&p_h2k, g_h2_keys);
    cudaGetSymbolAddress(&p_h2m, g_h2_min);
    cudaGetSymbolAddress(&p_hist, g_hist);
    cudaGetSymbolAddress(&p_cnt, g_cnt3);
    cudaGetSymbolAddress(&p_pool, g_pool);
    cudaGetSymbolAddress(&p_cp, g_cellpts);

    cudaMemsetAsync(p_h2k, 0xFF, (size_t)HSIZE * 8);
    cudaMemsetAsync(p_h2m, 0x7F, (size_t)HSIZE * 4);
    cudaMemsetAsync(p_hist, 0x00, (size_t)HIST_SIZE * 4);
    cudaMemsetAsync(p_cnt, 0x00, 4 * 4);
    cudaMemsetAsync(p_pool, 0x00, (size_t)TOPK * 27 * LF * 4);
    cudaMemsetAsync(p_cp, 0x00, (size_t)TOPK * 27 * 4);

    int nb = (N + 255) / 256;
    k_h2_insert<<<nb, 256>>>(coords, scores, N);
    k_peaks<<<nb, 256>>>(coords, scores, N);
    k_thresh<<<1, 1024>>>();
    k_collect<<<nb, 256>>>(N);
    k_select<<<1, 1024>>>(out);
    k_wc<<<1, TOPK>>>(coords, offs);
    k_match<<<nb, 256>>>(coords, offs, feats, N);
    k_cdesc<<<129, 96>>>(W, bg);

    if (base > 128) cudaMemsetAsync(out + 128, 0, (base - 128) * 4);

    cudaFuncSetAttribute(k_final, cudaFuncAttributeMaxDynamicSharedMemorySize, SMEM_FINAL);
    k_final<<<nb, 256, SMEM_FINAL>>>(feats, W, inst, N);
}

// round 10
// speedup vs baseline: 1.1440x; 1.1440x over previous
#include <cuda_runtime.h>
#include <cstdint>
#include <cstddef>

#define MAXN      262144
#define HBITS     19
#define HSIZE     (1u<<HBITS)
#define HMASK     (HSIZE-1u)
#define CH_BITS   14
#define CH_SIZE   (1u<<CH_BITS)
#define CH_MASK   (CH_SIZE-1u)
#define HIST_SIZE 262144
#define CAND_CAP  4096
#define LF        96
#define DF        32
#define TOPK      128
#define BPTS      256

typedef unsigned long long u64;

// ---------------- static scratch ---------------------------------------------
__device__ u64   g_h2[HSIZE];          // (cellkey<<18)|minIndex ; ~0 = empty
__device__ u64   g_cell[CH_SIZE];      // (cellkey<<16)|(k<<5)|o ; ~0 = empty
__device__ u64   g_comp[MAXN];
__device__ int   g_hist[HIST_SIZE];
__device__ u64   g_cand[CAND_CAP];
__device__ int   g_cnt3[4];
__device__ int   g_widx[TOPK];
__device__ float g_wconf[TOPK];
__device__ float g_pool[(size_t)TOPK*27*LF];
__device__ int   g_cellpts[TOPK*27];
__device__ float g_cdesc[129*DF];

// batch-blind key (reference int32 overflow kills the batch term); 30 bits
__device__ __forceinline__ u64 enc3(int x, int y, int z) {
    return ((u64)(unsigned)(x + 512) << 22) | ((u64)(unsigned)(y + 512) << 11)
         |  (u64)(unsigned)(z + 512);
}
__device__ __forceinline__ unsigned hash19(u64 k) {
    return (unsigned)((k * 0x9E3779B97F4A7C15ull) >> (64 - HBITS));
}
__device__ __forceinline__ unsigned hash14(u64 k) {
    return (unsigned)((k * 0x9E3779B97F4A7C15ull) >> (64 - CH_BITS));
}

// ---------------- fused init (replaces 6 memsets) ----------------------------
__global__ void k_init() {
    int i = blockIdx.x * blockDim.x + threadIdx.x;           // 524288 threads
    if (i < (int)HSIZE)      g_h2[i] = ~0ull;
    if (i < (int)CH_SIZE)    g_cell[i] = ~0ull;
    if (i < HIST_SIZE)       g_hist[i] = 0;
    if (i < TOPK*27)         g_cellpts[i] = 0;
    if (i < TOPK*27*LF)      g_pool[i] = 0.0f;
    if (i < 4)               g_cnt3[i] = 0;
}

// ---------------- h2 insert: per-cell min index over score>tau points --------
__global__ void k_h2_insert(const int* __restrict__ coords, const float* __restrict__ scores, int N) {
    int i = blockIdx.x * blockDim.x + threadIdx.x;
    if (i >= N) return;
    if (!(scores[i] > 0.1f)) return;
    int4 c = ((const int4*)coords)[i];
    u64 key = enc3(c.y, c.z, c.w);
    u64 w = (key << 18) | (unsigned)i;
    unsigned s = hash19(key);
    for (;;) {
        u64 cur = g_h2[s];
        if (cur == ~0ull) {
            u64 old = atomicCAS(&g_h2[s], ~0ull, w);
            if (old == ~0ull) return;
            cur = old;
        }
        if ((cur >> 18) == key) { atomicMin(&g_h2[s], w); return; }
        s = (s + 1) & HMASK;
    }
}

// ---------------- peaks: 27-tap max over per-cell representatives ------------
__global__ void k_peaks(const int* __restrict__ coords, const float* __restrict__ scores, int N) {
    int i = blockIdx.x * blockDim.x + threadIdx.x;
    if (i >= N) return;
    float sc = scores[i];
    if (!(sc > 0.1f)) { g_comp[i] = 0ull; return; }
    int4 c = ((const int4*)coords)[i];
    float hmax = -1.0f;
    #pragma unroll
    for (int dx = -1; dx <= 1; dx++)
    #pragma unroll
    for (int dy = -1; dy <= 1; dy++)
    #pragma unroll
    for (int dz = -1; dz <= 1; dz++) {
        u64 key = enc3(c.y+dx, c.z+dy, c.w+dz);
        unsigned s = hash19(key);
        for (;;) {
            u64 cur = g_h2[s];
            if (cur == ~0ull) break;
            if ((cur >> 18) == key) {
                hmax = fmaxf(hmax, scores[(int)(cur & 0x3FFFFu)]);
                break;
            }
            s = (s + 1) & HMASK;
        }
    }
    if (hmax == sc) {
        unsigned sb = __float_as_uint(sc);
        g_comp[i] = ((u64)sb << 32) | (u64)(0xFFFFFFFFu - (unsigned)i);
        atomicAdd(&g_hist[sb >> 12], 1);
    } else {
        g_comp[i] = 0ull;
    }
}

__global__ void k_thresh() {
    __shared__ int ssum[1024];
    __shared__ int cumsh;
    int t = threadIdx.x;
    if (t == 0) cumsh = 0;
    __syncthreads();
    for (int base = HIST_SIZE - 1024; base >= 0; base -= 1024) {
        ssum[t] = g_hist[base + t];
        __syncthreads();
        for (int o = 512; o > 0; o >>= 1) { if (t < o) ssum[t] += ssum[t + o]; __syncthreads(); }
        int chunk = ssum[0];
        int cum0 = cumsh;
        __syncthreads();
        if (cum0 + chunk >= TOPK) {
            if (t == 0) {
                int cum = cum0;
                for (int i2 = 1023; i2 >= 0; i2--) {
                    cum += g_hist[base + i2];
                    if (cum >= TOPK) { g_cnt3[2] = base + i2; break; }
                }
            }
            return;
        }
        if (t == 0) cumsh = cum0 + chunk;
        __syncthreads();
    }
}

__global__ void k_collect(int N) {
    int i = blockIdx.x * blockDim.x + threadIdx.x;
    if (i >= N) return;
    u64 c = g_comp[i];
    if (c == 0ull) return;
    if ((int)(c >> 44) >= g_cnt3[2]) {
        int p = atomicAdd(&g_cnt3[1], 1);
        if (p < CAND_CAP) g_cand[p] = c;
    }
}

// bitonic sort of next-pow2(n) candidates (desc), emit top-128 + conf
__global__ void k_select(float* __restrict__ conf_out) {
    __shared__ u64 s[CAND_CAP];
    int t = threadIdx.x; // 1024
    int n = g_cnt3[1]; if (n > CAND_CAP) n = CAND_CAP;
    int M = TOPK; while (M < n) M <<= 1;          // sort size
    for (int i = t; i < M; i += 1024) s[i] = (i < n) ? g_cand[i] : 0ull;
    __syncthreads();
    for (int k = 2; k <= M; k <<= 1) {
        for (int j = k >> 1; j > 0; j >>= 1) {
            for (int i = t; i < M; i += 1024) {
                int l = i ^ j;
                if (l > i) {
                    u64 a = s[i], b = s[l];
                    bool up = ((i & k) == 0);
                    if (up ? (a < b) : (a > b)) { s[i] = b; s[l] = a; }
                }
            }
            __syncthreads();
        }
    }
    if (t < TOPK) {
        u64 c = s[t];
        if (c != 0ull) {
            float sc = __uint_as_float((unsigned)(c >> 32));
            g_wconf[t] = sc;
            g_widx[t]  = (int)(0xFFFFFFFFu - (unsigned)(c & 0xFFFFFFFFull));
            conf_out[t] = sc;
        } else {
            g_wconf[t] = 0.0f; g_widx[t] = -1; conf_out[t] = 0.0f;
        }
    }
}

// ---------------- winner neighbor-cell hash: 128x27 entries ------------------
__global__ void k_cellhash(const int* __restrict__ coords, const float* __restrict__ offs) {
    int k = threadIdx.x;  // 128
    int idx = g_widx[k];
    if (idx < 0) return;
    int cx = coords[4*idx+1] + (int)offs[3*idx];
    int cy = coords[4*idx+2] + (int)offs[3*idx+1];
    int cz = coords[4*idx+3] + (int)offs[3*idx+2];
    for (int o = 0; o < 27; o++) {
        int dx = o/9 - 1, dy = (o/3)%3 - 1, dz = o%3 - 1;
        u64 key = enc3(cx+dx, cy+dy, cz+dz);
        u64 w = (key << 16) | (unsigned)((k << 5) | o);
        unsigned s = hash14(key);
        for (;;) {
            u64 old = atomicCAS(&g_cell[s], ~0ull, w);
            if (old == ~0ull) break;
            s = (s + 1) & CH_MASK;
        }
    }
}

// ---------------- point pass: one hash probe per point -----------------------
__global__ void k_match(const int* __restrict__ coords, const float* __restrict__ offs,
                        const float* __restrict__ feats, int N) {
    int i = blockIdx.x * blockDim.x + threadIdx.x;
    if (i >= N) return;
    int nx = coords[4*i+1] + (int)offs[3*i];
    int ny = coords[4*i+2] + (int)offs[3*i+1];
    int nz = coords[4*i+3] + (int)offs[3*i+2];
    u64 key = enc3(nx, ny, nz);
    unsigned s = hash14(key);
    for (;;) {
        u64 cur = g_cell[s];
        if (cur == ~0ull) return;
        if ((cur >> 16) == key) {
            int ko = (int)(cur & 0xFFFFu);
            int k = ko >> 5, o = ko & 31;
            atomicAdd(&g_cellpts[k*27 + o], 1);
            float* dst = &g_pool[((size_t)(k*27 + o))*LF];
            const float* src = feats + (size_t)i*LF;
            for (int l = 0; l < LF; l++) atomicAdd(&dst[l], src[l]);
        }
        s = (s + 1) & CH_MASK;
    }
}

// ---------------- winners: avg over occupied cells + tiny GEMM ---------------
__global__ void k_cdesc(const float* __restrict__ W, const float* __restrict__ bg) {
    int j = blockIdx.x;
    int t = threadIdx.x;  // 96
    __shared__ float pool[LF];
    if (j == 0) {
        if (t < DF) g_cdesc[t] = bg[t];
        return;
    }
    int k = j - 1;
    if (g_widx[k] < 0) {
        if (t < DF) g_cdesc[j*DF + t] = 0.0f;
        return;
    }
    float acc = 0.0f;
    int m = 0;
    #pragma unroll
    for (int o = 0; o < 27; o++) {
        int c = g_cellpts[k*27 + o];
        if (c > 0) { acc += g_pool[((size_t)(k*27 + o))*LF + t] / (float)c; m++; }
    }
    pool[t] = acc / (float)m;
    __syncthreads();
    if (t < DF) {
        float sacc = 0.0f;
        #pragma unroll 8
        for (int l = 0; l < LF; l++) sacc += pool[l] * W[l*DF + t];
        g_cdesc[j*DF + t] = fmaxf(sacc, 0.0f) * g_wconf[k];
    }
}

// ---------------- fused final on the packed f32x2 pipe -----------------------
__device__ __forceinline__ u64 pack2(float lo, float hi) {
    u64 r; asm("mov.b64 %0, {%1, %2};" : "=l"(r) : "f"(lo), "f"(hi)); return r;
}
__device__ __forceinline__ void unpack2(u64 v, float& lo, float& hi) {
    asm("mov.b64 {%0, %1}, %2;" : "=f"(lo), "=f"(hi) : "l"(v));
}
__device__ __forceinline__ u64 fma2(u64 a, u64 b, u64 c) {
    u64 r; asm("fma.rn.f32x2 %0, %1, %2, %3;" : "=l"(r) : "l"(a), "l"(b), "l"(c)); return r;
}

#define SMEM_SW   (LF*DF)
#define SMEM_SC   (129*36)
#define SMEM_SO   (BPTS*33)
#define SMEM_FINAL ((SMEM_SW + SMEM_SC + SMEM_SO) * (int)sizeof(float))

__global__ void k_final(const float* __restrict__ feats, const float* __restrict__ W,
                        float* __restrict__ inst, int N) {
    extern __shared__ float sm[];
    float* sW = sm;                     // [l*32+d], rows 128B
    float* sC = sm + SMEM_SW;           // [j*36+d], rows 144B (16B aligned)
    float* sO = sm + SMEM_SW + SMEM_SC; // staging [p*33+j0]
    int tid = threadIdx.x;
    for (int i = tid; i < LF*DF; i += BPTS) sW[i] = W[i];
    for (int i = tid; i < 129*36; i += BPTS) {
        int j = i / 36, d = i % 36;
        sC[i] = (d < DF) ? g_cdesc[j*DF + d] : 0.0f;
    }
    __syncthreads();

    int p0 = blockIdx.x * BPTS;
    int i = p0 + tid;
    u64 h2[16];
    #pragma unroll
    for (int d2 = 0; d2 < 16; d2++) h2[d2] = 0ull;

    if (i < N) {
        const float4* f4 = (const float4*)(feats + (size_t)i * LF);
        #pragma unroll 4
        for (int l4 = 0; l4 < LF/4; l4++) {
            float4 f = f4[l4];
            float fs[4] = {f.x, f.y, f.z, f.w};
            #pragma unroll
            for (int q = 0; q < 4; q++) {
                int l = l4*4 + q;
                u64 fb = pack2(fs[q], fs[q]);
                const ulonglong2* w2 = (const ulonglong2*)&sW[l*DF];
                #pragma unroll
                for (int p = 0; p < 8; p++) {
                    ulonglong2 wv = w2[p];
                    h2[p*2+0] = fma2(fb, wv.x, h2[p*2+0]);
                    h2[p*2+1] = fma2(fb, wv.y, h2[p*2+1]);
                }
            }
        }
        #pragma unroll
        for (int d2 = 0; d2 < 16; d2++) {
            float lo, hi; unpack2(h2[d2], lo, hi);
            h2[d2] = pack2(fmaxf(lo, 0.0f), fmaxf(hi, 0.0f));
        }
    }

    int np = N - p0; if (np > BPTS) np = BPTS;

    for (int jc = 0; jc < 128; jc += 32) {
        if (i < N) {
            #pragma unroll 4
            for (int jj = 0; jj < 32; jj++) {
                const ulonglong2* c2 = (const ulonglong2*)&sC[(jc+jj)*36];
                u64 acc = 0ull;
                #pragma unroll
                for (int p = 0; p < 8; p++) {
                    ulonglong2 cv = c2[p];
                    acc = fma2(h2[p*2+0], cv.x, acc);
                    acc = fma2(h2[p*2+1], cv.y, acc);
                }
                float lo, hi; unpack2(acc, lo, hi);
                sO[tid*33 + jj] = lo + hi;
            }
        }
        __syncthreads();
        for (int e = tid; e < np*32; e += BPTS) {
            int p = e >> 5, j0 = e & 31;
            inst[(size_t)(p0 + p) * 129 + jc + j0] = sO[p*33 + j0];
        }
        __syncthreads();
    }
    if (i < N) {
        const ulonglong2* c2 = (const ulonglong2*)&sC[128*36];
        u64 acc = 0ull;
        #pragma unroll
        for (int p = 0; p < 8; p++) {
            ulonglong2 cv = c2[p];
            acc = fma2(h2[p*2+0], cv.x, acc);
            acc = fma2(h2[p*2+1], cv.y, acc);
        }
        float lo, hi; unpack2(acc, lo, hi);
        inst[(size_t)i*129 + 128] = lo + hi;
    }
}

// ---------------- launch ------------------------------------------------------
extern "C" void kernel_launch(void* const* d_in, const int* in_sizes, int n_in,
                              void* d_out, int out_size) {
    const int*   coords = (const int*)d_in[0];
    const float* feats  = (const float*)d_in[1];
    const float* scores = (const float*)d_in[2];
    const float* offs   = (const float*)d_in[3];
    const float* W      = (const float*)d_in[4];
    const float* bg     = (const float*)d_in[5];
    int N = in_sizes[0] / 4;
    float* out = (float*)d_out;
    size_t base = (size_t)out_size - (size_t)N * 129;
    float* inst = out + base;

    int nb = (N + 255) / 256;
    k_init<<<2048, 256>>>();
    k_h2_insert<<<nb, 256>>>(coords, scores, N);
    k_peaks<<<nb, 256>>>(coords, scores, N);
    k_thresh<<<1, 1024>>>();
    k_collect<<<nb, 256>>>(N);
    k_select<<<1, 1024>>>(out);
    k_cellhash<<<1, TOPK>>>(coords, offs);
    k_match<<<nb, 256>>>(coords, offs, feats, N);
    k_cdesc<<<129, 96>>>(W, bg);

    if (base > 128) cudaMemsetAsync(out + 128, 0, (base - 128) * 4);

    cudaFuncSetAttribute(k_final, cudaFuncAttributeMaxDynamicSharedMemorySize, SMEM_FINAL);
    k_final<<<nb, 256, SMEM_FINAL>>>(feats, W, inst, N);
}

// round 11
// speedup vs baseline: 1.1664x; 1.0196x over previous
#include <cuda_runtime.h>
#include <cstdint>
#include <cstddef>

#define MAXN      262144
#define HBITS     19
#define HSIZE     (1u<<HBITS)
#define HMASK     (HSIZE-1u)
#define CH_BITS   14
#define CH_SIZE   (1u<<CH_BITS)
#define CH_MASK   (CH_SIZE-1u)
#define HIST_SIZE 262144
#define CAND_CAP  4096
#define LF        96
#define DF        32
#define TOPK      128
#define BPTS      256

typedef unsigned long long u64;

// ---------------- static scratch ---------------------------------------------
__device__ u64   g_h2[HSIZE];          // (cellkey<<18)|minIndex ; ~0 = empty
__device__ u64   g_cell[CH_SIZE];      // (cellkey<<16)|(k<<5)|o ; ~0 = empty
__device__ u64   g_comp[MAXN];
__device__ int   g_hist[HIST_SIZE];
__device__ u64   g_cand[CAND_CAP];
__device__ int   g_cnt3[4];
__device__ int   g_widx[TOPK];
__device__ float g_wconf[TOPK];
__device__ float g_pool[(size_t)TOPK*27*LF];
__device__ int   g_cellpts[TOPK*27];
__device__ float g_cdesc[129*DF];
__device__ float g_H[(size_t)MAXN*DF];  // hidden activations relu(F@W)

// batch-blind key (reference int32 overflow kills the batch term); 30 bits
__device__ __forceinline__ u64 enc3(int x, int y, int z) {
    return ((u64)(unsigned)(x + 512) << 22) | ((u64)(unsigned)(y + 512) << 11)
         |  (u64)(unsigned)(z + 512);
}
__device__ __forceinline__ unsigned hash19(u64 k) {
    return (unsigned)((k * 0x9E3779B97F4A7C15ull) >> (64 - HBITS));
}
__device__ __forceinline__ unsigned hash14(u64 k) {
    return (unsigned)((k * 0x9E3779B97F4A7C15ull) >> (64 - CH_BITS));
}

__device__ __forceinline__ u64 pack2(float lo, float hi) {
    u64 r; asm("mov.b64 %0, {%1, %2};" : "=l"(r) : "f"(lo), "f"(hi)); return r;
}
__device__ __forceinline__ void unpack2(u64 v, float& lo, float& hi) {
    asm("mov.b64 {%0, %1}, %2;" : "=f"(lo), "=f"(hi) : "l"(v));
}
__device__ __forceinline__ u64 fma2(u64 a, u64 b, u64 c) {
    u64 r; asm("fma.rn.f32x2 %0, %1, %2, %3;" : "=l"(r) : "l"(a), "l"(b), "l"(c)); return r;
}

// ---------------- fused init --------------------------------------------------
__global__ void k_init() {
    int i = blockIdx.x * blockDim.x + threadIdx.x;           // 524288 threads
    if (i < (int)HSIZE)      g_h2[i] = ~0ull;
    if (i < (int)CH_SIZE)    g_cell[i] = ~0ull;
    if (i < HIST_SIZE)       g_hist[i] = 0;
    if (i < TOPK*27)         g_cellpts[i] = 0;
    if (i < TOPK*27*LF)      g_pool[i] = 0.0f;
    if (i < 4)               g_cnt3[i] = 0;
}

// ---------------- h2 insert: per-cell min index over score>tau points --------
__global__ void k_h2_insert(const int* __restrict__ coords, const float* __restrict__ scores, int N) {
    int i = blockIdx.x * blockDim.x + threadIdx.x;
    if (i >= N) return;
    if (!(scores[i] > 0.1f)) return;
    int4 c = ((const int4*)coords)[i];
    u64 key = enc3(c.y, c.z, c.w);
    u64 w = (key << 18) | (unsigned)i;
    unsigned s = hash19(key);
    for (;;) {
        u64 cur = g_h2[s];
        if (cur == ~0ull) {
            u64 old = atomicCAS(&g_h2[s], ~0ull, w);
            if (old == ~0ull) return;
            cur = old;
        }
        if ((cur >> 18) == key) { atomicMin(&g_h2[s], w); return; }
        s = (s + 1) & HMASK;
    }
}

// ---------------- peaks: 27-tap max over per-cell representatives ------------
__global__ void k_peaks(const int* __restrict__ coords, const float* __restrict__ scores, int N) {
    int i = blockIdx.x * blockDim.x + threadIdx.x;
    if (i >= N) return;
    float sc = scores[i];
    if (!(sc > 0.1f)) { g_comp[i] = 0ull; return; }
    int4 c = ((const int4*)coords)[i];
    float hmax = -1.0f;
    #pragma unroll
    for (int dx = -1; dx <= 1; dx++)
    #pragma unroll
    for (int dy = -1; dy <= 1; dy++)
    #pragma unroll
    for (int dz = -1; dz <= 1; dz++) {
        u64 key = enc3(c.y+dx, c.z+dy, c.w+dz);
        unsigned s = hash19(key);
        for (;;) {
            u64 cur = g_h2[s];
            if (cur == ~0ull) break;
            if ((cur >> 18) == key) {
                hmax = fmaxf(hmax, scores[(int)(cur & 0x3FFFFu)]);
                break;
            }
            s = (s + 1) & HMASK;
        }
    }
    if (hmax == sc) {
        unsigned sb = __float_as_uint(sc);
        g_comp[i] = ((u64)sb << 32) | (u64)(0xFFFFFFFFu - (unsigned)i);
        atomicAdd(&g_hist[sb >> 12], 1);
    } else {
        g_comp[i] = 0ull;
    }
}

// scores < 1.0 => max bucket = 0x3F7FFFFF>>12 = 260095 => first useful chunk base
#define THRESH_BASE0 ((260095/1024)*1024)

__global__ void k_thresh() {
    __shared__ int ssum[1024];
    __shared__ int cumsh;
    int t = threadIdx.x;
    if (t == 0) cumsh = 0;
    __syncthreads();
    for (int base = THRESH_BASE0; base >= 0; base -= 1024) {
        ssum[t] = g_hist[base + t];
        __syncthreads();
        for (int o = 512; o > 0; o >>= 1) { if (t < o) ssum[t] += ssum[t + o]; __syncthreads(); }
        int chunk = ssum[0];
        int cum0 = cumsh;
        __syncthreads();
        if (cum0 + chunk >= TOPK) {
            if (t == 0) {
                int cum = cum0;
                for (int i2 = 1023; i2 >= 0; i2--) {
                    cum += g_hist[base + i2];
                    if (cum >= TOPK) { g_cnt3[2] = base + i2; break; }
                }
            }
            return;
        }
        if (t == 0) cumsh = cum0 + chunk;
        __syncthreads();
    }
}

__global__ void k_collect(int N) {
    int i = blockIdx.x * blockDim.x + threadIdx.x;
    if (i >= N) return;
    u64 c = g_comp[i];
    if (c == 0ull) return;
    if ((int)(c >> 44) >= g_cnt3[2]) {
        int p = atomicAdd(&g_cnt3[1], 1);
        if (p < CAND_CAP) g_cand[p] = c;
    }
}

// bitonic sort (desc), emit top-128 + conf, then build winner-cell hash
__global__ void k_select(float* __restrict__ conf_out,
                         const int* __restrict__ coords, const float* __restrict__ offs) {
    __shared__ u64 s[CAND_CAP];
    int t = threadIdx.x; // 1024
    int n = g_cnt3[1]; if (n > CAND_CAP) n = CAND_CAP;
    int M = TOPK; while (M < n) M <<= 1;
    for (int i = t; i < M; i += 1024) s[i] = (i < n) ? g_cand[i] : 0ull;
    __syncthreads();
    for (int k = 2; k <= M; k <<= 1) {
        for (int j = k >> 1; j > 0; j >>= 1) {
            for (int i = t; i < M; i += 1024) {
                int l = i ^ j;
                if (l > i) {
                    u64 a = s[i], b = s[l];
                    bool up = ((i & k) == 0);
                    if (up ? (a < b) : (a > b)) { s[i] = b; s[l] = a; }
                }
            }
            __syncthreads();
        }
    }
    int widx = -1;
    if (t < TOPK) {
        u64 c = s[t];
        if (c != 0ull) {
            float sc = __uint_as_float((unsigned)(c >> 32));
            g_wconf[t] = sc;
            widx = (int)(0xFFFFFFFFu - (unsigned)(c & 0xFFFFFFFFull));
            g_widx[t] = widx;
            conf_out[t] = sc;
        } else {
            g_wconf[t] = 0.0f; g_widx[t] = -1; conf_out[t] = 0.0f;
        }
    }
    // winner neighbor-cell hash (threads 0..127)
    if (t < TOPK && widx >= 0) {
        int idx = widx;
        int cx = coords[4*idx+1] + (int)offs[3*idx];
        int cy = coords[4*idx+2] + (int)offs[3*idx+1];
        int cz = coords[4*idx+3] + (int)offs[3*idx+2];
        for (int o = 0; o < 27; o++) {
            int dx = o/9 - 1, dy = (o/3)%3 - 1, dz = o%3 - 1;
            u64 key = enc3(cx+dx, cy+dy, cz+dz);
            u64 w = (key << 16) | (unsigned)((t << 5) | o);
            unsigned h = hash14(key);
            for (;;) {
                u64 old = atomicCAS(&g_cell[h], ~0ull, w);
                if (old == ~0ull) break;
                h = (h + 1) & CH_MASK;
            }
        }
    }
}

// ---------------- point pass: one hash probe per point -----------------------
__global__ void k_match(const int* __restrict__ coords, const float* __restrict__ offs,
                        const float* __restrict__ feats, int N) {
    int i = blockIdx.x * blockDim.x + threadIdx.x;
    if (i >= N) return;
    int4 c = ((const int4*)coords)[i];
    int nx = c.y + (int)offs[3*i];
    int ny = c.z + (int)offs[3*i+1];
    int nz = c.w + (int)offs[3*i+2];
    u64 key = enc3(nx, ny, nz);
    unsigned s = hash14(key);
    for (;;) {
        u64 cur = g_cell[s];
        if (cur == ~0ull) return;
        if ((cur >> 16) == key) {
            int ko = (int)(cur & 0xFFFFu);
            int k = ko >> 5, o = ko & 31;
            atomicAdd(&g_cellpts[k*27 + o], 1);
            float* dst = &g_pool[((size_t)(k*27 + o))*LF];
            const float* src = feats + (size_t)i*LF;
            for (int l = 0; l < LF; l++) atomicAdd(&dst[l], src[l]);
        }
        s = (s + 1) & CH_MASK;
    }
}

// ---------------- winners: avg over occupied cells + tiny GEMM ---------------
__global__ void k_cdesc(const float* __restrict__ W, const float* __restrict__ bg) {
    int j = blockIdx.x;
    int t = threadIdx.x;  // 96
    __shared__ float pool[LF];
    if (j == 0) {
        if (t < DF) g_cdesc[t] = bg[t];
        return;
    }
    int k = j - 1;
    if (g_widx[k] < 0) {
        if (t < DF) g_cdesc[j*DF + t] = 0.0f;
        return;
    }
    float acc = 0.0f;
    int m = 0;
    #pragma unroll
    for (int o = 0; o < 27; o++) {
        int c = g_cellpts[k*27 + o];
        if (c > 0) { acc += g_pool[((size_t)(k*27 + o))*LF + t] / (float)c; m++; }
    }
    pool[t] = acc / (float)m;
    __syncthreads();
    if (t < DF) {
        float sacc = 0.0f;
        #pragma unroll 8
        for (int l = 0; l < LF; l++) sacc += pool[l] * W[l*DF + t];
        g_cdesc[j*DF + t] = fmaxf(sacc, 0.0f) * g_wconf[k];
    }
}

// ---------------- hidden: H = relu(F @ W), independent of peak chain ---------
__global__ void k_hidden(const float* __restrict__ feats, const float* __restrict__ W, int N) {
    __shared__ float sW[LF*DF];
    int tid = threadIdx.x;
    for (int i = tid; i < LF*DF; i += BPTS) sW[i] = W[i];
    __syncthreads();
    int i = blockIdx.x * BPTS + tid;
    if (i >= N) return;
    u64 h2[16];
    #pragma unroll
    for (int d2 = 0; d2 < 16; d2++) h2[d2] = 0ull;
    const float4* f4 = (const float4*)(feats + (size_t)i * LF);
    #pragma unroll 4
    for (int l4 = 0; l4 < LF/4; l4++) {
        float4 f = f4[l4];
        float fs[4] = {f.x, f.y, f.z, f.w};
        #pragma unroll
        for (int q = 0; q < 4; q++) {
            u64 fb = pack2(fs[q], fs[q]);
            const ulonglong2* w2 = (const ulonglong2*)&sW[(l4*4+q)*DF];
            #pragma unroll
            for (int p = 0; p < 8; p++) {
                ulonglong2 wv = w2[p];
                h2[p*2+0] = fma2(fb, wv.x, h2[p*2+0]);
                h2[p*2+1] = fma2(fb, wv.y, h2[p*2+1]);
            }
        }
    }
    ulonglong2* out2 = (ulonglong2*)&g_H[(size_t)i*DF];
    #pragma unroll
    for (int p = 0; p < 8; p++) {
        float a, b, c, d;
        unpack2(h2[p*2+0], a, b); unpack2(h2[p*2+1], c, d);
        ulonglong2 v;
        v.x = pack2(fmaxf(a, 0.0f), fmaxf(b, 0.0f));
        v.y = pack2(fmaxf(c, 0.0f), fmaxf(d, 0.0f));
        out2[p] = v;
    }
}

// ---------------- inst = H @ cdesc^T -----------------------------------------
#define SMEM_SC   (129*36)
#define SMEM_SO   (BPTS*33)
#define SMEM_INST ((SMEM_SC + SMEM_SO) * (int)sizeof(float))

__global__ void k_inst(float* __restrict__ inst, int N) {
    extern __shared__ float sm[];
    float* sC = sm;
    float* sO = sm + SMEM_SC;
    int tid = threadIdx.x;
    for (int i = tid; i < 129*36; i += BPTS) {
        int j = i / 36, d = i % 36;
        sC[i] = (d < DF) ? g_cdesc[j*DF + d] : 0.0f;
    }
    __syncthreads();

    int p0 = blockIdx.x * BPTS;
    int i = p0 + tid;
    u64 h2[16];
    if (i < N) {
        const ulonglong2* in2 = (const ulonglong2*)&g_H[(size_t)i*DF];
        #pragma unroll
        for (int p = 0; p < 8; p++) {
            ulonglong2 v = in2[p];
            h2[p*2+0] = v.x; h2[p*2+1] = v.y;
        }
    }

    int np = N - p0; if (np > BPTS) np = BPTS;

    for (int jc = 0; jc < 128; jc += 32) {
        if (i < N) {
            #pragma unroll 4
            for (int jj = 0; jj < 32; jj++) {
                const ulonglong2* c2 = (const ulonglong2*)&sC[(jc+jj)*36];
                u64 acc = 0ull;
                #pragma unroll
                for (int p = 0; p < 8; p++) {
                    ulonglong2 cv = c2[p];
                    acc = fma2(h2[p*2+0], cv.x, acc);
                    acc = fma2(h2[p*2+1], cv.y, acc);
                }
                float lo, hi; unpack2(acc, lo, hi);
                sO[tid*33 + jj] = lo + hi;
            }
        }
        __syncthreads();
        for (int e = tid; e < np*32; e += BPTS) {
            int p = e >> 5, j0 = e & 31;
            inst[(size_t)(p0 + p) * 129 + jc + j0] = sO[p*33 + j0];
        }
        __syncthreads();
    }
    if (i < N) {
        const ulonglong2* c2 = (const ulonglong2*)&sC[128*36];
        u64 acc = 0ull;
        #pragma unroll
        for (int p = 0; p < 8; p++) {
            ulonglong2 cv = c2[p];
            acc = fma2(h2[p*2+0], cv.x, acc);
            acc = fma2(h2[p*2+1], cv.y, acc);
        }
        float lo, hi; unpack2(acc, lo, hi);
        inst[(size_t)i*129 + 128] = lo + hi;
    }
}

// ---------------- launch ------------------------------------------------------
extern "C" void kernel_launch(void* const* d_in, const int* in_sizes, int n_in,
                              void* d_out, int out_size) {
    const int*   coords = (const int*)d_in[0];
    const float* feats  = (const float*)d_in[1];
    const float* scores = (const float*)d_in[2];
    const float* offs   = (const float*)d_in[3];
    const float* W      = (const float*)d_in[4];
    const float* bg     = (const float*)d_in[5];
    int N = in_sizes[0] / 4;
    float* out = (float*)d_out;
    size_t base = (size_t)out_size - (size_t)N * 129;
    float* inst = out + base;

    static cudaStream_t s2 = nullptr;
    static cudaEvent_t evFork = nullptr, evHidden = nullptr;
    if (s2 == nullptr) {
        cudaStreamCreateWithFlags(&s2, cudaStreamNonBlocking);
        cudaEventCreateWithFlags(&evFork, cudaEventDisableTiming);
        cudaEventCreateWithFlags(&evHidden, cudaEventDisableTiming);
        cudaFuncSetAttribute(k_inst, cudaFuncAttributeMaxDynamicSharedMemorySize, SMEM_INST);
    }

    int nb = (N + 255) / 256;

    // fork: hidden GEMM runs concurrently with the peak/cluster chain
    cudaEventRecord(evFork, 0);
    cudaStreamWaitEvent(s2, evFork, 0);
    k_hidden<<<nb, 256, 0, s2>>>(feats, W, N);
    cudaEventRecord(evHidden, s2);

    // peak / cluster chain on the main stream
    k_init<<<2048, 256>>>();
    k_h2_insert<<<nb, 256>>>(coords, scores, N);
    k_peaks<<<nb, 256>>>(coords, scores, N);
    k_thresh<<<1, 1024>>>();
    k_collect<<<nb, 256>>>(N);
    k_select<<<1, 1024>>>(out, coords, offs);
    k_match<<<nb, 256>>>(coords, offs, feats, N);
    k_cdesc<<<129, 96>>>(W, bg);

    if (base > 128) cudaMemsetAsync(out + 128, 0, (base - 128) * 4);

    // join: inst needs cdesc (main stream) + hidden (s2)
    cudaStreamWaitEvent(0, evHidden, 0);
    k_inst<<<nb, 256, SMEM_INST>>>(inst, N);
}